// round 1
// baseline (speedup 1.0000x reference)
#include <cuda_runtime.h>
#include <cstdint>
#include <cstddef>

// Problem constants
#define NN 512
#define SD 256
#define ND 128
#define ED 16

// ---------------- scratch (static device globals; no allocation) ----------------
__device__ float g_ef[NN * NN * ED];   // edge features, dst-major: [j][i][t]  (16.7 MB)
__device__ float g_n[NN * ND];         // node features after projector+LN
__device__ float g_n2[NN * ND];        // node features after MPN layer 1
__device__ float g_A[NN * ND];         // n @ mW_src
__device__ float g_B[NN * ND];         // n @ mW_dst + mb
__device__ float g_agg[NN * ND];       // aggregated messages
__device__ float g_P[NN * 64];         // n @ Wc1[:128]
__device__ float g_Q[NN * 64];         // n @ Wc1[128:] + bc1

// ---------------- packed f32x2 helpers (sm_103a FFMA2 path) ----------------
__device__ __forceinline__ unsigned long long pack2(float lo, float hi) {
    unsigned long long r;
    asm("mov.b64 %0, {%1, %2};" : "=l"(r) : "f"(lo), "f"(hi));
    return r;
}
__device__ __forceinline__ void unpack2(unsigned long long v, float& lo, float& hi) {
    asm("mov.b64 {%0, %1}, %2;" : "=f"(lo), "=f"(hi) : "l"(v));
}
__device__ __forceinline__ unsigned long long fma2(unsigned long long a,
                                                   unsigned long long b,
                                                   unsigned long long c) {
    unsigned long long d;
    asm("fma.rn.f32x2 %0, %1, %2, %3;" : "=l"(d) : "l"(a), "l"(b), "l"(c));
    return d;
}
__device__ __forceinline__ unsigned long long add2(unsigned long long a,
                                                   unsigned long long b) {
    unsigned long long d;
    asm("add.rn.f32x2 %0, %1, %2;" : "=l"(d) : "l"(a), "l"(b));
    return d;
}

// ---------------- K1: spatial projector + LayerNorm -> g_n ----------------
__global__ __launch_bounds__(128) void k_node_mlp(
    const float* __restrict__ X,
    const float* __restrict__ W1, const float* __restrict__ b1,
    const float* __restrict__ W2, const float* __restrict__ b2,
    const float* __restrict__ lng, const float* __restrict__ lnb)
{
    constexpr int NB = 4;
    __shared__ float xs[NB][SD];
    __shared__ float h1[NB][ND];
    __shared__ float ssum[NB][4], ssq[NB][4];

    const int k = threadIdx.x;          // feature index 0..127
    const int n0 = blockIdx.x * NB;

    for (int idx = k; idx < NB * SD; idx += 128) {
        xs[idx / SD][idx % SD] = X[n0 * SD + idx];
    }
    __syncthreads();

    float acc[NB];
#pragma unroll
    for (int nd = 0; nd < NB; nd++) acc[nd] = 0.f;
    for (int t = 0; t < SD; t++) {
        float w = W1[t * ND + k];
#pragma unroll
        for (int nd = 0; nd < NB; nd++) acc[nd] += xs[nd][t] * w;
    }
    float bb = b1[k];
#pragma unroll
    for (int nd = 0; nd < NB; nd++) h1[nd][k] = fmaxf(acc[nd] + bb, 0.f);
    __syncthreads();

#pragma unroll
    for (int nd = 0; nd < NB; nd++) acc[nd] = 0.f;
    for (int t = 0; t < ND; t++) {
        float w = W2[t * ND + k];
#pragma unroll
        for (int nd = 0; nd < NB; nd++) acc[nd] += h1[nd][t] * w;
    }
    float b2k = b2[k];
#pragma unroll
    for (int nd = 0; nd < NB; nd++) acc[nd] += b2k;

    // LayerNorm over features (k) per node
    const int warp = k >> 5, lane = k & 31;
#pragma unroll
    for (int nd = 0; nd < NB; nd++) {
        float v = acc[nd], v2 = v * v;
        for (int o = 16; o > 0; o >>= 1) {
            v  += __shfl_xor_sync(0xffffffffu, v,  o);
            v2 += __shfl_xor_sync(0xffffffffu, v2, o);
        }
        if (lane == 0) { ssum[nd][warp] = v; ssq[nd][warp] = v2; }
    }
    __syncthreads();
    float gk = lng[k], bk = lnb[k];
#pragma unroll
    for (int nd = 0; nd < NB; nd++) {
        float s = ssum[nd][0] + ssum[nd][1] + ssum[nd][2] + ssum[nd][3];
        float q = ssq[nd][0] + ssq[nd][1] + ssq[nd][2] + ssq[nd][3];
        float mu = s * (1.0f / ND);
        float var = q * (1.0f / ND) - mu * mu;
        float r = rsqrtf(var + 1e-5f);
        g_n[(n0 + nd) * ND + k] = (acc[nd] - mu) * r * gk + bk;
    }
}

// ---------------- K2: edge geometry + edge encoder -> g_ef[j][i][t] ----------------
__global__ __launch_bounds__(128) void k_edge(
    const float* __restrict__ pos,
    const float* __restrict__ We1, const float* __restrict__ be1,
    const float* __restrict__ We2, const float* __restrict__ be2)
{
    __shared__ float w1s[64], b1s[16], w2s[256], b2s[16];
    const int tid = threadIdx.x;
    if (tid < 64) w1s[tid] = We1[tid];
    for (int idx = tid; idx < 256; idx += 128) w2s[idx] = We2[idx];
    if (tid < 16) { b1s[tid] = be1[tid]; b2s[tid] = be2[tid]; }

    const int j = blockIdx.x;   // dst
    const float pjx = pos[j * 2], pjy = pos[j * 2 + 1];
    __syncthreads();

    for (int i = tid; i < NN; i += 128) {   // src
        float4* o4 = (float4*)&g_ef[((size_t)j * NN + i) * ED];
        if (i == j) {
            float4 z = make_float4(0.f, 0.f, 0.f, 0.f);
            o4[0] = z; o4[1] = z; o4[2] = z; o4[3] = z;
            continue;
        }
        const float pix = pos[i * 2], piy = pos[i * 2 + 1];
        const float dx = pjx - pix, dy = pjy - piy;        // dst - src
        const float dist = sqrtf(dx * dx + dy * dy);
        const float ang = atan2f(dy, dx);
        float h[16];
#pragma unroll
        for (int u = 0; u < 16; u++) {
            float a = pix * w1s[u] + piy * w1s[16 + u] + dist * w1s[32 + u]
                    + ang * w1s[48 + u] + b1s[u];
            h[u] = fmaxf(a, 0.f);
        }
        float o[16];
#pragma unroll
        for (int v = 0; v < 16; v++) {
            float a = b2s[v];
#pragma unroll
            for (int u = 0; u < 16; u++) a += h[u] * w2s[u * 16 + v];
            o[v] = tanhf(a);
        }
        o4[0] = make_float4(o[0], o[1], o[2], o[3]);
        o4[1] = make_float4(o[4], o[5], o[6], o[7]);
        o4[2] = make_float4(o[8], o[9], o[10], o[11]);
        o4[3] = make_float4(o[12], o[13], o[14], o[15]);
    }
}

// ---------------- K3: A = n@mW_src,  B = n@mW_dst + mb ----------------
__global__ __launch_bounds__(128) void k_ab(
    const float* __restrict__ nin,
    const float* __restrict__ mW, const float* __restrict__ mb)
{
    constexpr int NB = 4;
    __shared__ float xs[NB][ND];
    const int k = threadIdx.x;
    const int n0 = blockIdx.x * NB;
    for (int idx = k; idx < NB * ND; idx += 128)
        xs[idx >> 7][idx & 127] = nin[n0 * ND + idx];
    __syncthreads();
    float a[NB], b[NB];
#pragma unroll
    for (int nd = 0; nd < NB; nd++) { a[nd] = 0.f; b[nd] = 0.f; }
    for (int t = 0; t < ND; t++) {
        float wA = mW[t * ND + k];
        float wB = mW[(ND + t) * ND + k];
#pragma unroll
        for (int nd = 0; nd < NB; nd++) {
            float x = xs[nd][t];
            a[nd] += x * wA;
            b[nd] += x * wB;
        }
    }
    float bias = mb[k];
#pragma unroll
    for (int nd = 0; nd < NB; nd++) {
        g_A[(n0 + nd) * ND + k] = a[nd];
        g_B[(n0 + nd) * ND + k] = b[nd] + bias;
    }
}

// ---------------- K4: fused ef-matvec + relu + segment-sum  -> g_agg ----------------
// block = 128 threads = two dst nodes (64 threads each); thread owns feature pair (2t,2t+1)
__global__ __launch_bounds__(128) void k_agg(const float* __restrict__ mW)
{
    constexpr int TI = 32;
    __shared__ __align__(16) float efs[2][TI * ED * 2];  // ef values duplicated pairwise
    const int grp = threadIdx.x >> 6;
    const int t64 = threadIdx.x & 63;
    const int j = blockIdx.x * 2 + grp;
    const int k0 = t64 * 2;

    unsigned long long Wp[ED];
#pragma unroll
    for (int t = 0; t < ED; t++) {
        float2 w = *(const float2*)&mW[(2 * ND + t) * ND + k0];
        Wp[t] = pack2(w.x, w.y);
    }
    float2 bj = *(const float2*)&g_B[j * ND + k0];
    const unsigned long long Bp = pack2(bj.x, bj.y);
    const unsigned long long Z  = pack2(0.f, 0.f);

    float acc0 = 0.f, acc1 = 0.f;
    for (int i0 = 0; i0 < NN; i0 += TI) {
        __syncthreads();
        const float4* src = (const float4*)&g_ef[((size_t)j * NN + i0) * ED];
#pragma unroll
        for (int r = 0; r < 2; r++) {
            int idx = t64 + 64 * r;
            float4 v = src[idx];
            float4* dst = (float4*)&efs[grp][idx * 8];
            dst[0] = make_float4(v.x, v.x, v.y, v.y);
            dst[1] = make_float4(v.z, v.z, v.w, v.w);
        }
        __syncthreads();
#pragma unroll 2
        for (int ii = 0; ii < TI; ii++) {
            const int i = i0 + ii;
            float2 a = *(const float2*)&g_A[i * ND + k0];
            const ulonglong2* ep = (const ulonglong2*)&efs[grp][ii * 32];
            ulonglong2 q0 = ep[0], q1 = ep[1], q2 = ep[2], q3 = ep[3];
            ulonglong2 q4 = ep[4], q5 = ep[5], q6 = ep[6], q7 = ep[7];
            unsigned long long e0 = Bp, e1 = Z, e2 = Z, e3 = Z;
            e0 = fma2(q0.x, Wp[0],  e0);  e1 = fma2(q0.y, Wp[1],  e1);
            e2 = fma2(q1.x, Wp[2],  e2);  e3 = fma2(q1.y, Wp[3],  e3);
            e0 = fma2(q2.x, Wp[4],  e0);  e1 = fma2(q2.y, Wp[5],  e1);
            e2 = fma2(q3.x, Wp[6],  e2);  e3 = fma2(q3.y, Wp[7],  e3);
            e0 = fma2(q4.x, Wp[8],  e0);  e1 = fma2(q4.y, Wp[9],  e1);
            e2 = fma2(q5.x, Wp[10], e2);  e3 = fma2(q5.y, Wp[11], e3);
            e0 = fma2(q6.x, Wp[12], e0);  e1 = fma2(q6.y, Wp[13], e1);
            e2 = fma2(q7.x, Wp[14], e2);  e3 = fma2(q7.y, Wp[15], e3);
            unsigned long long ec = add2(add2(e0, e1), add2(e2, e3));
            unsigned long long v  = add2(ec, pack2(a.x, a.y));
            float v0, v1;
            unpack2(v, v0, v1);
            if (i != j) {
                acc0 += fmaxf(v0, 0.f);
                acc1 += fmaxf(v1, 0.f);
            }
        }
    }
    g_agg[j * ND + k0]     = acc0;
    g_agg[j * ND + k0 + 1] = acc1;
}

// ---------------- K5: update MLP  n_out = relu([n, agg] @ uW + ub) ----------------
__global__ __launch_bounds__(128) void k_upd(
    const float* __restrict__ nin,
    const float* __restrict__ uW, const float* __restrict__ ub,
    float* __restrict__ nout)
{
    constexpr int NB = 4;
    __shared__ float xs[NB][2 * ND];
    const int k = threadIdx.x;
    const int n0 = blockIdx.x * NB;
    for (int idx = k; idx < NB * ND; idx += 128) {
        int nd = idx >> 7, t = idx & 127;
        xs[nd][t]      = nin[(n0 + nd) * ND + t];
        xs[nd][ND + t] = g_agg[(n0 + nd) * ND + t];
    }
    __syncthreads();
    float acc[NB];
#pragma unroll
    for (int nd = 0; nd < NB; nd++) acc[nd] = 0.f;
    for (int t = 0; t < 2 * ND; t++) {
        float w = uW[t * ND + k];
#pragma unroll
        for (int nd = 0; nd < NB; nd++) acc[nd] += xs[nd][t] * w;
    }
    float bb = ub[k];
#pragma unroll
    for (int nd = 0; nd < NB; nd++)
        nout[(n0 + nd) * ND + k] = fmaxf(acc[nd] + bb, 0.f);
}

// ---------------- K6: P = n@Wc1[:128],  Q = n@Wc1[128:] + bc1 ----------------
__global__ __launch_bounds__(64) void k_pq(
    const float* __restrict__ nin,
    const float* __restrict__ Wc1, const float* __restrict__ bc1)
{
    constexpr int NB = 8;
    __shared__ float xs[NB][ND];
    const int k = threadIdx.x;      // 0..63
    const int n0 = blockIdx.x * NB;
    for (int idx = k; idx < NB * ND; idx += 64)
        xs[idx >> 7][idx & 127] = nin[n0 * ND + idx];
    __syncthreads();
    float p[NB], q[NB];
#pragma unroll
    for (int nd = 0; nd < NB; nd++) { p[nd] = 0.f; q[nd] = 0.f; }
    for (int t = 0; t < ND; t++) {
        float wp = Wc1[t * 64 + k];
        float wq = Wc1[(ND + t) * 64 + k];
#pragma unroll
        for (int nd = 0; nd < NB; nd++) {
            float x = xs[nd][t];
            p[nd] += x * wp;
            q[nd] += x * wq;
        }
    }
    float bb = bc1[k];
#pragma unroll
    for (int nd = 0; nd < NB; nd++) {
        g_P[(n0 + nd) * 64 + k] = p[nd];
        g_Q[(n0 + nd) * 64 + k] = q[nd] + bb;
    }
}

// ---------------- K7: pairwise scores (relu(P_i+Q_j) @ Wc2 -> sigmoid) ----------------
__global__ __launch_bounds__(256) void k_scores(
    const float* __restrict__ Wc2, const float* __restrict__ bc2,
    float* __restrict__ out)
{
    __shared__ float Ps[16][65], Qs[16][65], ws[64];
    const int tid = threadIdx.x;
    const int tx = tid & 15, ty = tid >> 4;
    const int j0 = blockIdx.x * 16, i0 = blockIdx.y * 16;

    for (int idx = tid; idx < 16 * 64; idx += 256) {
        int r = idx >> 6, c = idx & 63;
        Ps[r][c] = g_P[(i0 + r) * 64 + c];
        Qs[r][c] = g_Q[(j0 + r) * 64 + c];
    }
    if (tid < 64) ws[tid] = Wc2[tid];
    __syncthreads();

    float acc = 0.f;
#pragma unroll 8
    for (int t = 0; t < 64; t++)
        acc += fmaxf(Ps[ty][t] + Qs[tx][t], 0.f) * ws[t];
    acc += bc2[0];
    float s = 1.f / (1.f + expf(-acc));
    const int i = i0 + ty, j = j0 + tx;
    out[i * NN + j] = (i == j) ? 0.f : s;
}

// ---------------- launch ----------------
extern "C" void kernel_launch(void* const* d_in, const int* in_sizes, int n_in,
                              void* d_out, int out_size)
{
    const float* X   = (const float*)d_in[0];
    const float* pos = (const float*)d_in[1];
    const float* W1  = (const float*)d_in[2];
    const float* b1  = (const float*)d_in[3];
    const float* W2  = (const float*)d_in[4];
    const float* b2  = (const float*)d_in[5];
    const float* lng = (const float*)d_in[6];
    const float* lnb = (const float*)d_in[7];
    const float* We1 = (const float*)d_in[8];
    const float* be1 = (const float*)d_in[9];
    const float* We2 = (const float*)d_in[10];
    const float* be2 = (const float*)d_in[11];
    const float* mW1 = (const float*)d_in[12];
    const float* mb1 = (const float*)d_in[13];
    const float* uW1 = (const float*)d_in[14];
    const float* ub1 = (const float*)d_in[15];
    const float* mW2 = (const float*)d_in[16];
    const float* mb2 = (const float*)d_in[17];
    const float* uW2 = (const float*)d_in[18];
    const float* ub2 = (const float*)d_in[19];
    const float* Wc1 = (const float*)d_in[20];
    const float* bc1 = (const float*)d_in[21];
    const float* Wc2 = (const float*)d_in[22];
    const float* bc2 = (const float*)d_in[23];

    float* out   = (float*)d_out;
    float* out_n = out;             // [512*128] node features
    float* out_s = out + NN * ND;   // [512*512] scores

    float *pN = nullptr, *pN2 = nullptr;
    cudaGetSymbolAddress((void**)&pN,  g_n);
    cudaGetSymbolAddress((void**)&pN2, g_n2);

    k_node_mlp<<<128, 128>>>(X, W1, b1, W2, b2, lng, lnb);
    k_edge<<<512, 128>>>(pos, We1, be1, We2, be2);

    // MPN layer 1
    k_ab<<<128, 128>>>(pN, mW1, mb1);
    k_agg<<<256, 128>>>(mW1);
    k_upd<<<128, 128>>>(pN, uW1, ub1, pN2);

    // MPN layer 2 (final node features written straight into d_out)
    k_ab<<<128, 128>>>(pN2, mW2, mb2);
    k_agg<<<256, 128>>>(mW2);
    k_upd<<<128, 128>>>(pN2, uW2, ub2, out_n);

    // classifier
    k_pq<<<64, 64>>>(out_n, Wc1, bc1);
    k_scores<<<dim3(32, 32), 256>>>(Wc2, bc2, out_s);
}

// round 2
// speedup vs baseline: 1.3570x; 1.3570x over previous
#include <cuda_runtime.h>
#include <cstdint>
#include <cstddef>

// Problem constants
#define NN 512
#define SD 256
#define ND 128
#define ED 16
#define NCH 4              // i-chunks per dst node in k_agg
#define CHSZ (NN / NCH)    // 128 i's per chunk

// ---------------- scratch (static device globals; no allocation) ----------------
__device__ float g_ef[NN * NN * ED];        // edge features, dst-major: [j][i][t]  (16.7 MB)
__device__ float g_n[NN * ND];              // node features after projector+LN
__device__ float g_n2[NN * ND];             // node features after MPN layer 1
__device__ float g_A[NN * ND];              // n @ mW_src
__device__ float g_B[NN * ND];              // n @ mW_dst + mb
__device__ float g_aggp[NCH][NN * ND];      // partial aggregated messages (per i-chunk)
__device__ float g_P[NN * 64];              // n @ Wc1[:128]
__device__ float g_Q[NN * 64];              // n @ Wc1[128:] + bc1

// ---------------- packed f32x2 helpers (sm_103a FFMA2 path) ----------------
__device__ __forceinline__ unsigned long long pack2(float lo, float hi) {
    unsigned long long r;
    asm("mov.b64 %0, {%1, %2};" : "=l"(r) : "f"(lo), "f"(hi));
    return r;
}
__device__ __forceinline__ void unpack2(unsigned long long v, float& lo, float& hi) {
    asm("mov.b64 {%0, %1}, %2;" : "=f"(lo), "=f"(hi) : "l"(v));
}
__device__ __forceinline__ unsigned long long fma2(unsigned long long a,
                                                   unsigned long long b,
                                                   unsigned long long c) {
    unsigned long long d;
    asm("fma.rn.f32x2 %0, %1, %2, %3;" : "=l"(d) : "l"(a), "l"(b), "l"(c));
    return d;
}
__device__ __forceinline__ unsigned long long add2(unsigned long long a,
                                                   unsigned long long b) {
    unsigned long long d;
    asm("add.rn.f32x2 %0, %1, %2;" : "=l"(d) : "l"(a), "l"(b));
    return d;
}

// ---------------- K1: spatial projector + LayerNorm -> g_n ----------------
__global__ __launch_bounds__(128) void k_node_mlp(
    const float* __restrict__ X,
    const float* __restrict__ W1, const float* __restrict__ b1,
    const float* __restrict__ W2, const float* __restrict__ b2,
    const float* __restrict__ lng, const float* __restrict__ lnb)
{
    constexpr int NB = 4;
    __shared__ float xs[NB][SD];
    __shared__ float h1[NB][ND];
    __shared__ float ssum[NB][4], ssq[NB][4];

    const int k = threadIdx.x;          // feature index 0..127
    const int n0 = blockIdx.x * NB;

    for (int idx = k; idx < NB * SD; idx += 128) {
        xs[idx / SD][idx % SD] = X[n0 * SD + idx];
    }
    __syncthreads();

    float acc[NB];
#pragma unroll
    for (int nd = 0; nd < NB; nd++) acc[nd] = 0.f;
    for (int t = 0; t < SD; t++) {
        float w = W1[t * ND + k];
#pragma unroll
        for (int nd = 0; nd < NB; nd++) acc[nd] += xs[nd][t] * w;
    }
    float bb = b1[k];
#pragma unroll
    for (int nd = 0; nd < NB; nd++) h1[nd][k] = fmaxf(acc[nd] + bb, 0.f);
    __syncthreads();

#pragma unroll
    for (int nd = 0; nd < NB; nd++) acc[nd] = 0.f;
    for (int t = 0; t < ND; t++) {
        float w = W2[t * ND + k];
#pragma unroll
        for (int nd = 0; nd < NB; nd++) acc[nd] += h1[nd][t] * w;
    }
    float b2k = b2[k];
#pragma unroll
    for (int nd = 0; nd < NB; nd++) acc[nd] += b2k;

    // LayerNorm over features (k) per node
    const int warp = k >> 5, lane = k & 31;
#pragma unroll
    for (int nd = 0; nd < NB; nd++) {
        float v = acc[nd], v2 = v * v;
        for (int o = 16; o > 0; o >>= 1) {
            v  += __shfl_xor_sync(0xffffffffu, v,  o);
            v2 += __shfl_xor_sync(0xffffffffu, v2, o);
        }
        if (lane == 0) { ssum[nd][warp] = v; ssq[nd][warp] = v2; }
    }
    __syncthreads();
    float gk = lng[k], bk = lnb[k];
#pragma unroll
    for (int nd = 0; nd < NB; nd++) {
        float s = ssum[nd][0] + ssum[nd][1] + ssum[nd][2] + ssum[nd][3];
        float q = ssq[nd][0] + ssq[nd][1] + ssq[nd][2] + ssq[nd][3];
        float mu = s * (1.0f / ND);
        float var = q * (1.0f / ND) - mu * mu;
        float r = rsqrtf(var + 1e-5f);
        g_n[(n0 + nd) * ND + k] = (acc[nd] - mu) * r * gk + bk;
    }
}

// ---------------- K2: edge geometry + edge encoder -> g_ef[j][i][t] ----------------
__global__ __launch_bounds__(128) void k_edge(
    const float* __restrict__ pos,
    const float* __restrict__ We1, const float* __restrict__ be1,
    const float* __restrict__ We2, const float* __restrict__ be2)
{
    __shared__ float w1s[64], b1s[16], w2s[256], b2s[16];
    const int tid = threadIdx.x;
    if (tid < 64) w1s[tid] = We1[tid];
    for (int idx = tid; idx < 256; idx += 128) w2s[idx] = We2[idx];
    if (tid < 16) { b1s[tid] = be1[tid]; b2s[tid] = be2[tid]; }

    const int j = blockIdx.x;   // dst
    const float pjx = pos[j * 2], pjy = pos[j * 2 + 1];
    __syncthreads();

    for (int i = tid; i < NN; i += 128) {   // src
        float4* o4 = (float4*)&g_ef[((size_t)j * NN + i) * ED];
        if (i == j) {
            float4 z = make_float4(0.f, 0.f, 0.f, 0.f);
            o4[0] = z; o4[1] = z; o4[2] = z; o4[3] = z;
            continue;
        }
        const float pix = pos[i * 2], piy = pos[i * 2 + 1];
        const float dx = pjx - pix, dy = pjy - piy;        // dst - src
        const float dist = sqrtf(dx * dx + dy * dy);
        const float ang = atan2f(dy, dx);
        float h[16];
#pragma unroll
        for (int u = 0; u < 16; u++) {
            float a = pix * w1s[u] + piy * w1s[16 + u] + dist * w1s[32 + u]
                    + ang * w1s[48 + u] + b1s[u];
            h[u] = fmaxf(a, 0.f);
        }
        float o[16];
#pragma unroll
        for (int v = 0; v < 16; v++) {
            float a = b2s[v];
#pragma unroll
            for (int u = 0; u < 16; u++) a += h[u] * w2s[u * 16 + v];
            o[v] = tanhf(a);
        }
        o4[0] = make_float4(o[0], o[1], o[2], o[3]);
        o4[1] = make_float4(o[4], o[5], o[6], o[7]);
        o4[2] = make_float4(o[8], o[9], o[10], o[11]);
        o4[3] = make_float4(o[12], o[13], o[14], o[15]);
    }
}

// ---------------- K3: A = n@mW_src,  B = n@mW_dst + mb ----------------
__global__ __launch_bounds__(128) void k_ab(
    const float* __restrict__ nin,
    const float* __restrict__ mW, const float* __restrict__ mb)
{
    constexpr int NB = 4;
    __shared__ float xs[NB][ND];
    const int k = threadIdx.x;
    const int n0 = blockIdx.x * NB;
    for (int idx = k; idx < NB * ND; idx += 128)
        xs[idx >> 7][idx & 127] = nin[n0 * ND + idx];
    __syncthreads();
    float a[NB], b[NB];
#pragma unroll
    for (int nd = 0; nd < NB; nd++) { a[nd] = 0.f; b[nd] = 0.f; }
    for (int t = 0; t < ND; t++) {
        float wA = mW[t * ND + k];
        float wB = mW[(ND + t) * ND + k];
#pragma unroll
        for (int nd = 0; nd < NB; nd++) {
            float x = xs[nd][t];
            a[nd] += x * wA;
            b[nd] += x * wB;
        }
    }
    float bias = mb[k];
#pragma unroll
    for (int nd = 0; nd < NB; nd++) {
        g_A[(n0 + nd) * ND + k] = a[nd];
        g_B[(n0 + nd) * ND + k] = b[nd] + bias;
    }
}

// ---------------- K4: fused ef-matvec + relu + segment-sum (partial) ----------------
// grid = (512 dst j, NCH i-chunks). block = 128 threads: two 64-thread groups,
// each group handles 64 i's for the SAME j; thread owns feature pair (2t, 2t+1).
__global__ __launch_bounds__(128) void k_agg(const float* __restrict__ mW)
{
    __shared__ __align__(16) float efs[2][64 * ED * 2];  // ef duplicated pairwise, 16 KB
    __shared__ float part[ND];

    const int grp = threadIdx.x >> 6;
    const int t64 = threadIdx.x & 63;
    const int j = blockIdx.x;
    const int i0 = blockIdx.y * CHSZ + grp * 64;   // this group's 64 i's
    const int k0 = t64 * 2;

    unsigned long long Wp[ED];
#pragma unroll
    for (int t = 0; t < ED; t++) {
        float2 w = *(const float2*)&mW[(2 * ND + t) * ND + k0];
        Wp[t] = pack2(w.x, w.y);
    }
    float2 bj = *(const float2*)&g_B[j * ND + k0];
    const unsigned long long Bp = pack2(bj.x, bj.y);
    const unsigned long long Z  = pack2(0.f, 0.f);

    // stage this group's 64 i's of ef (duplicated pairwise) — single barrier
    {
        const float4* src = (const float4*)&g_ef[((size_t)j * NN + i0) * ED];
#pragma unroll
        for (int r = 0; r < 4; r++) {
            int idx = t64 + 64 * r;            // 0..255 float4s (64 i * 4)
            float4 v = src[idx];
            float4* dst = (float4*)&efs[grp][idx * 8];
            dst[0] = make_float4(v.x, v.x, v.y, v.y);
            dst[1] = make_float4(v.z, v.z, v.w, v.w);
        }
    }
    __syncthreads();

    float acc0 = 0.f, acc1 = 0.f;
#pragma unroll 2
    for (int ii = 0; ii < 64; ii++) {
        const int i = i0 + ii;
        float2 a = *(const float2*)&g_A[i * ND + k0];
        const ulonglong2* ep = (const ulonglong2*)&efs[grp][ii * 32];
        ulonglong2 q0 = ep[0], q1 = ep[1], q2 = ep[2], q3 = ep[3];
        ulonglong2 q4 = ep[4], q5 = ep[5], q6 = ep[6], q7 = ep[7];
        unsigned long long e0 = Bp, e1 = Z, e2 = Z, e3 = Z;
        e0 = fma2(q0.x, Wp[0],  e0);  e1 = fma2(q0.y, Wp[1],  e1);
        e2 = fma2(q1.x, Wp[2],  e2);  e3 = fma2(q1.y, Wp[3],  e3);
        e0 = fma2(q2.x, Wp[4],  e0);  e1 = fma2(q2.y, Wp[5],  e1);
        e2 = fma2(q3.x, Wp[6],  e2);  e3 = fma2(q3.y, Wp[7],  e3);
        e0 = fma2(q4.x, Wp[8],  e0);  e1 = fma2(q4.y, Wp[9],  e1);
        e2 = fma2(q5.x, Wp[10], e2);  e3 = fma2(q5.y, Wp[11], e3);
        e0 = fma2(q6.x, Wp[12], e0);  e1 = fma2(q6.y, Wp[13], e1);
        e2 = fma2(q7.x, Wp[14], e2);  e3 = fma2(q7.y, Wp[15], e3);
        unsigned long long ec = add2(add2(e0, e1), add2(e2, e3));
        unsigned long long v  = add2(ec, pack2(a.x, a.y));
        float v0, v1;
        unpack2(v, v0, v1);
        if (i != j) {
            acc0 += fmaxf(v0, 0.f);
            acc1 += fmaxf(v1, 0.f);
        }
    }

    // combine the two groups' partials, write one partial row per (chunk, j)
    if (grp == 1) { part[k0] = acc0; part[k0 + 1] = acc1; }
    __syncthreads();
    if (grp == 0) {
        g_aggp[blockIdx.y][j * ND + k0]     = acc0 + part[k0];
        g_aggp[blockIdx.y][j * ND + k0 + 1] = acc1 + part[k0 + 1];
    }
}

// ---------------- K5: update MLP  n_out = relu([n, sum(aggp)] @ uW + ub) ----------------
__global__ __launch_bounds__(128) void k_upd(
    const float* __restrict__ nin,
    const float* __restrict__ uW, const float* __restrict__ ub,
    float* __restrict__ nout)
{
    constexpr int NB = 4;
    __shared__ float xs[NB][2 * ND];
    const int k = threadIdx.x;
    const int n0 = blockIdx.x * NB;
    for (int idx = k; idx < NB * ND; idx += 128) {
        int nd = idx >> 7, t = idx & 127;
        int off = (n0 + nd) * ND + t;
        xs[nd][t]      = nin[off];
        xs[nd][ND + t] = g_aggp[0][off] + g_aggp[1][off]
                       + g_aggp[2][off] + g_aggp[3][off];
    }
    __syncthreads();
    float acc[NB];
#pragma unroll
    for (int nd = 0; nd < NB; nd++) acc[nd] = 0.f;
    for (int t = 0; t < 2 * ND; t++) {
        float w = uW[t * ND + k];
#pragma unroll
        for (int nd = 0; nd < NB; nd++) acc[nd] += xs[nd][t] * w;
    }
    float bb = ub[k];
#pragma unroll
    for (int nd = 0; nd < NB; nd++)
        nout[(n0 + nd) * ND + k] = fmaxf(acc[nd] + bb, 0.f);
}

// ---------------- K6: P = n@Wc1[:128],  Q = n@Wc1[128:] + bc1 ----------------
__global__ __launch_bounds__(64) void k_pq(
    const float* __restrict__ nin,
    const float* __restrict__ Wc1, const float* __restrict__ bc1)
{
    constexpr int NB = 8;
    __shared__ float xs[NB][ND];
    const int k = threadIdx.x;      // 0..63
    const int n0 = blockIdx.x * NB;
    for (int idx = k; idx < NB * ND; idx += 64)
        xs[idx >> 7][idx & 127] = nin[n0 * ND + idx];
    __syncthreads();
    float p[NB], q[NB];
#pragma unroll
    for (int nd = 0; nd < NB; nd++) { p[nd] = 0.f; q[nd] = 0.f; }
    for (int t = 0; t < ND; t++) {
        float wp = Wc1[t * 64 + k];
        float wq = Wc1[(ND + t) * 64 + k];
#pragma unroll
        for (int nd = 0; nd < NB; nd++) {
            float x = xs[nd][t];
            p[nd] += x * wp;
            q[nd] += x * wq;
        }
    }
    float bb = bc1[k];
#pragma unroll
    for (int nd = 0; nd < NB; nd++) {
        g_P[(n0 + nd) * 64 + k] = p[nd];
        g_Q[(n0 + nd) * 64 + k] = q[nd] + bb;
    }
}

// ---------------- K7: pairwise scores (relu(P_i+Q_j) @ Wc2 -> sigmoid) ----------------
__global__ __launch_bounds__(256) void k_scores(
    const float* __restrict__ Wc2, const float* __restrict__ bc2,
    float* __restrict__ out)
{
    __shared__ float Ps[16][65], Qs[16][65], ws[64];
    const int tid = threadIdx.x;
    const int tx = tid & 15, ty = tid >> 4;
    const int j0 = blockIdx.x * 16, i0 = blockIdx.y * 16;

    for (int idx = tid; idx < 16 * 64; idx += 256) {
        int r = idx >> 6, c = idx & 63;
        Ps[r][c] = g_P[(i0 + r) * 64 + c];
        Qs[r][c] = g_Q[(j0 + r) * 64 + c];
    }
    if (tid < 64) ws[tid] = Wc2[tid];
    __syncthreads();

    float acc = 0.f;
#pragma unroll 8
    for (int t = 0; t < 64; t++)
        acc += fmaxf(Ps[ty][t] + Qs[tx][t], 0.f) * ws[t];
    acc += bc2[0];
    float s = 1.f / (1.f + expf(-acc));
    const int i = i0 + ty, j = j0 + tx;
    out[i * NN + j] = (i == j) ? 0.f : s;
}

// ---------------- launch ----------------
extern "C" void kernel_launch(void* const* d_in, const int* in_sizes, int n_in,
                              void* d_out, int out_size)
{
    const float* X   = (const float*)d_in[0];
    const float* pos = (const float*)d_in[1];
    const float* W1  = (const float*)d_in[2];
    const float* b1  = (const float*)d_in[3];
    const float* W2  = (const float*)d_in[4];
    const float* b2  = (const float*)d_in[5];
    const float* lng = (const float*)d_in[6];
    const float* lnb = (const float*)d_in[7];
    const float* We1 = (const float*)d_in[8];
    const float* be1 = (const float*)d_in[9];
    const float* We2 = (const float*)d_in[10];
    const float* be2 = (const float*)d_in[11];
    const float* mW1 = (const float*)d_in[12];
    const float* mb1 = (const float*)d_in[13];
    const float* uW1 = (const float*)d_in[14];
    const float* ub1 = (const float*)d_in[15];
    const float* mW2 = (const float*)d_in[16];
    const float* mb2 = (const float*)d_in[17];
    const float* uW2 = (const float*)d_in[18];
    const float* ub2 = (const float*)d_in[19];
    const float* Wc1 = (const float*)d_in[20];
    const float* bc1 = (const float*)d_in[21];
    const float* Wc2 = (const float*)d_in[22];
    const float* bc2 = (const float*)d_in[23];

    float* out   = (float*)d_out;
    float* out_n = out;             // [512*128] node features
    float* out_s = out + NN * ND;   // [512*512] scores

    float *pN = nullptr, *pN2 = nullptr;
    cudaGetSymbolAddress((void**)&pN,  g_n);
    cudaGetSymbolAddress((void**)&pN2, g_n2);

    k_node_mlp<<<128, 128>>>(X, W1, b1, W2, b2, lng, lnb);
    k_edge<<<512, 128>>>(pos, We1, be1, We2, be2);

    // MPN layer 1
    k_ab<<<128, 128>>>(pN, mW1, mb1);
    k_agg<<<dim3(512, NCH), 128>>>(mW1);
    k_upd<<<128, 128>>>(pN, uW1, ub1, pN2);

    // MPN layer 2 (final node features written straight into d_out)
    k_ab<<<128, 128>>>(pN2, mW2, mb2);
    k_agg<<<dim3(512, NCH), 128>>>(mW2);
    k_upd<<<128, 128>>>(pN2, uW2, ub2, out_n);

    // classifier
    k_pq<<<64, 64>>>(out_n, Wc1, bc1);
    k_scores<<<dim3(32, 32), 256>>>(Wc2, bc2, out_s);
}

// round 3
// speedup vs baseline: 2.0046x; 1.4772x over previous
#include <cuda_runtime.h>
#include <cstdint>
#include <cstddef>

// Problem constants
#define NN 512
#define SD 256
#define ND 128
#define ED 16
#define CH 64               // i's per chunk in k_agg
#define NCH2 (NN / CH)      // 8 chunks

// ---------------- scratch (static device globals; no allocation) ----------------
__device__ float g_efd[NN * NN * 32];       // edge features, duplicated pairs: [j][i][t][2] (33.5 MB)
__device__ float g_n[NN * ND];              // node features after projector+LN
__device__ float g_n2[NN * ND];             // node features after MPN layer 1
__device__ float g_A[NN * ND];              // n @ mW_src
__device__ float g_B[NN * ND];              // n @ mW_dst + mb
__device__ float g_aggp[NCH2][NN * ND];     // partial aggregated messages (per i-chunk)
__device__ float g_P[NN * 64];              // n @ Wc1[:128]
__device__ float g_Q[NN * 64];              // n @ Wc1[128:] + bc1

// ---------------- packed f32x2 helpers (sm_103a FFMA2 path) ----------------
__device__ __forceinline__ unsigned long long pack2(float lo, float hi) {
    unsigned long long r;
    asm("mov.b64 %0, {%1, %2};" : "=l"(r) : "f"(lo), "f"(hi));
    return r;
}
__device__ __forceinline__ void unpack2(unsigned long long v, float& lo, float& hi) {
    asm("mov.b64 {%0, %1}, %2;" : "=f"(lo), "=f"(hi) : "l"(v));
}
__device__ __forceinline__ unsigned long long fma2(unsigned long long a,
                                                   unsigned long long b,
                                                   unsigned long long c) {
    unsigned long long d;
    asm("fma.rn.f32x2 %0, %1, %2, %3;" : "=l"(d) : "l"(a), "l"(b), "l"(c));
    return d;
}
__device__ __forceinline__ unsigned long long add2(unsigned long long a,
                                                   unsigned long long b) {
    unsigned long long d;
    asm("add.rn.f32x2 %0, %1, %2;" : "=l"(d) : "l"(a), "l"(b));
    return d;
}
__device__ __forceinline__ float tanh_fast(float x) {
    float y;
    asm("tanh.approx.f32 %0, %1;" : "=f"(y) : "f"(x));
    return y;
}

// ---------------- K1 (fused): spatial projector+LN  |  edge encoder ----------------
// blocks [0,256): node MLP, 2 nodes/block. blocks [256,768): edge encoder, j = bx-256.
__global__ __launch_bounds__(128) void k_pre(
    const float* __restrict__ X,
    const float* __restrict__ W1, const float* __restrict__ b1,
    const float* __restrict__ W2, const float* __restrict__ b2,
    const float* __restrict__ lng, const float* __restrict__ lnb,
    const float* __restrict__ pos,
    const float* __restrict__ We1, const float* __restrict__ be1,
    const float* __restrict__ We2, const float* __restrict__ be2)
{
    if (blockIdx.x < 256) {
        // ---- node MLP + LayerNorm ----
        constexpr int NB = 2;
        __shared__ float xs[NB][SD];
        __shared__ float h1[NB][ND];
        __shared__ float ssum[NB][4], ssq[NB][4];

        const int k = threadIdx.x;
        const int n0 = blockIdx.x * NB;

        for (int idx = k; idx < NB * SD; idx += 128)
            xs[idx / SD][idx % SD] = X[n0 * SD + idx];
        __syncthreads();

        float acc[NB];
#pragma unroll
        for (int nd = 0; nd < NB; nd++) acc[nd] = 0.f;
        for (int t = 0; t < SD; t++) {
            float w = W1[t * ND + k];
#pragma unroll
            for (int nd = 0; nd < NB; nd++) acc[nd] += xs[nd][t] * w;
        }
        float bb = b1[k];
#pragma unroll
        for (int nd = 0; nd < NB; nd++) h1[nd][k] = fmaxf(acc[nd] + bb, 0.f);
        __syncthreads();

#pragma unroll
        for (int nd = 0; nd < NB; nd++) acc[nd] = 0.f;
        for (int t = 0; t < ND; t++) {
            float w = W2[t * ND + k];
#pragma unroll
            for (int nd = 0; nd < NB; nd++) acc[nd] += h1[nd][t] * w;
        }
        float b2k = b2[k];
#pragma unroll
        for (int nd = 0; nd < NB; nd++) acc[nd] += b2k;

        const int warp = k >> 5, lane = k & 31;
#pragma unroll
        for (int nd = 0; nd < NB; nd++) {
            float v = acc[nd], v2 = v * v;
            for (int o = 16; o > 0; o >>= 1) {
                v  += __shfl_xor_sync(0xffffffffu, v,  o);
                v2 += __shfl_xor_sync(0xffffffffu, v2, o);
            }
            if (lane == 0) { ssum[nd][warp] = v; ssq[nd][warp] = v2; }
        }
        __syncthreads();
        float gk = lng[k], bk = lnb[k];
#pragma unroll
        for (int nd = 0; nd < NB; nd++) {
            float s = ssum[nd][0] + ssum[nd][1] + ssum[nd][2] + ssum[nd][3];
            float q = ssq[nd][0] + ssq[nd][1] + ssq[nd][2] + ssq[nd][3];
            float mu = s * (1.0f / ND);
            float var = q * (1.0f / ND) - mu * mu;
            float r = rsqrtf(var + 1e-5f);
            g_n[(n0 + nd) * ND + k] = (acc[nd] - mu) * r * gk + bk;
        }
    } else {
        // ---- edge encoder: writes duplicated-pair layout ----
        __shared__ float w1s[64], b1s[16], w2s[256], b2s[16];
        const int tid = threadIdx.x;
        if (tid < 64) w1s[tid] = We1[tid];
        for (int idx = tid; idx < 256; idx += 128) w2s[idx] = We2[idx];
        if (tid < 16) { b1s[tid] = be1[tid]; b2s[tid] = be2[tid]; }

        const int j = blockIdx.x - 256;
        const float pjx = pos[j * 2], pjy = pos[j * 2 + 1];
        __syncthreads();

        for (int i = tid; i < NN; i += 128) {
            float4* o4 = (float4*)&g_efd[((size_t)j * NN + i) * 32];
            if (i == j) {
                float4 z = make_float4(0.f, 0.f, 0.f, 0.f);
#pragma unroll
                for (int r = 0; r < 8; r++) o4[r] = z;
                continue;
            }
            const float pix = pos[i * 2], piy = pos[i * 2 + 1];
            const float dx = pjx - pix, dy = pjy - piy;
            const float dist = sqrtf(dx * dx + dy * dy);
            const float ang = atan2f(dy, dx);
            float h[16];
#pragma unroll
            for (int u = 0; u < 16; u++) {
                float a = pix * w1s[u] + piy * w1s[16 + u] + dist * w1s[32 + u]
                        + ang * w1s[48 + u] + b1s[u];
                h[u] = fmaxf(a, 0.f);
            }
            float o[16];
#pragma unroll
            for (int v = 0; v < 16; v++) {
                float a = b2s[v];
#pragma unroll
                for (int u = 0; u < 16; u++) a += h[u] * w2s[u * 16 + v];
                o[v] = tanh_fast(a);
            }
#pragma unroll
            for (int r = 0; r < 8; r++)
                o4[r] = make_float4(o[2 * r], o[2 * r], o[2 * r + 1], o[2 * r + 1]);
        }
    }
}

// ---------------- K3: A = n@mW_src,  B = n@mW_dst + mb ----------------
__global__ __launch_bounds__(128) void k_ab(
    const float* __restrict__ nin,
    const float* __restrict__ mW, const float* __restrict__ mb)
{
    constexpr int NB = 2;
    __shared__ float xs[NB][ND];
    const int k = threadIdx.x;
    const int n0 = blockIdx.x * NB;
    for (int idx = k; idx < NB * ND; idx += 128)
        xs[idx >> 7][idx & 127] = nin[n0 * ND + idx];
    __syncthreads();
    float a[NB], b[NB];
#pragma unroll
    for (int nd = 0; nd < NB; nd++) { a[nd] = 0.f; b[nd] = 0.f; }
    for (int t = 0; t < ND; t++) {
        float wA = mW[t * ND + k];
        float wB = mW[(ND + t) * ND + k];
#pragma unroll
        for (int nd = 0; nd < NB; nd++) {
            float x = xs[nd][t];
            a[nd] += x * wA;
            b[nd] += x * wB;
        }
    }
    float bias = mb[k];
#pragma unroll
    for (int nd = 0; nd < NB; nd++) {
        g_A[(n0 + nd) * ND + k] = a[nd];
        g_B[(n0 + nd) * ND + k] = b[nd] + bias;
    }
}

// ---------------- K4: fused ef-matvec + relu + segment-sum (partial) ----------------
// block = 128 threads = 4 warps, each warp one dst j; thread covers 4 features:
// (2*lane, 2*lane+1) and (64+2*lane, 65+2*lane), each as one packed f32x2 chain.
// grid = (128 j-quads, NCH2 i-chunks of CH=64 i's).
__global__ __launch_bounds__(128) void k_agg(const float* __restrict__ mW)
{
    __shared__ __align__(16) float efs[4][CH * 32];   // 4 warps * 8 KB = 32 KB

    const int grp  = threadIdx.x >> 5;
    const int lane = threadIdx.x & 31;
    const int j  = blockIdx.x * 4 + grp;
    const int i0 = blockIdx.y * CH;
    const int kA = 2 * lane;
    const int kB = 64 + 2 * lane;

    unsigned long long WA[ED], WB[ED];
#pragma unroll
    for (int t = 0; t < ED; t++) {
        float2 wa = *(const float2*)&mW[(2 * ND + t) * ND + kA];
        float2 wb = *(const float2*)&mW[(2 * ND + t) * ND + kB];
        WA[t] = pack2(wa.x, wa.y);
        WB[t] = pack2(wb.x, wb.y);
    }
    float2 ba = *(const float2*)&g_B[j * ND + kA];
    float2 bb = *(const float2*)&g_B[j * ND + kB];
    const unsigned long long BA = pack2(ba.x, ba.y);
    const unsigned long long BB = pack2(bb.x, bb.y);

    // stage this warp's CH i's of duplicated ef (8 KB) — coalesced copy
    {
        const float4* src = (const float4*)&g_efd[((size_t)j * NN + i0) * 32];
        float4* dst = (float4*)efs[grp];
#pragma unroll
        for (int r = 0; r < 16; r++)
            dst[lane + 32 * r] = src[lane + 32 * r];
    }
    __syncthreads();

    float a0 = 0.f, a1 = 0.f, a2 = 0.f, a3 = 0.f;
#pragma unroll 2
    for (int ii = 0; ii < CH; ii++) {
        const int i = i0 + ii;
        float2 aA = *(const float2*)&g_A[i * ND + kA];
        float2 aB = *(const float2*)&g_A[i * ND + kB];
        const ulonglong2* ep = (const ulonglong2*)&efs[grp][ii * 32];
        ulonglong2 q0 = ep[0], q1 = ep[1], q2 = ep[2], q3 = ep[3];
        ulonglong2 q4 = ep[4], q5 = ep[5], q6 = ep[6], q7 = ep[7];

        unsigned long long eA0 = BA, eA1 = pack2(aA.x, aA.y);
        unsigned long long eB0 = BB, eB1 = pack2(aB.x, aB.y);
        eA0 = fma2(q0.x, WA[0],  eA0);  eA1 = fma2(q0.y, WA[1],  eA1);
        eB0 = fma2(q0.x, WB[0],  eB0);  eB1 = fma2(q0.y, WB[1],  eB1);
        eA0 = fma2(q1.x, WA[2],  eA0);  eA1 = fma2(q1.y, WA[3],  eA1);
        eB0 = fma2(q1.x, WB[2],  eB0);  eB1 = fma2(q1.y, WB[3],  eB1);
        eA0 = fma2(q2.x, WA[4],  eA0);  eA1 = fma2(q2.y, WA[5],  eA1);
        eB0 = fma2(q2.x, WB[4],  eB0);  eB1 = fma2(q2.y, WB[5],  eB1);
        eA0 = fma2(q3.x, WA[6],  eA0);  eA1 = fma2(q3.y, WA[7],  eA1);
        eB0 = fma2(q3.x, WB[6],  eB0);  eB1 = fma2(q3.y, WB[7],  eB1);
        eA0 = fma2(q4.x, WA[8],  eA0);  eA1 = fma2(q4.y, WA[9],  eA1);
        eB0 = fma2(q4.x, WB[8],  eB0);  eB1 = fma2(q4.y, WB[9],  eB1);
        eA0 = fma2(q5.x, WA[10], eA0);  eA1 = fma2(q5.y, WA[11], eA1);
        eB0 = fma2(q5.x, WB[10], eB0);  eB1 = fma2(q5.y, WB[11], eB1);
        eA0 = fma2(q6.x, WA[12], eA0);  eA1 = fma2(q6.y, WA[13], eA1);
        eB0 = fma2(q6.x, WB[12], eB0);  eB1 = fma2(q6.y, WB[13], eB1);
        eA0 = fma2(q7.x, WA[14], eA0);  eA1 = fma2(q7.y, WA[15], eA1);
        eB0 = fma2(q7.x, WB[14], eB0);  eB1 = fma2(q7.y, WB[15], eB1);

        unsigned long long vA = add2(eA0, eA1);
        unsigned long long vB = add2(eB0, eB1);
        float v0, v1, v2, v3;
        unpack2(vA, v0, v1);
        unpack2(vB, v2, v3);
        if (i != j) {
            a0 += fmaxf(v0, 0.f);
            a1 += fmaxf(v1, 0.f);
            a2 += fmaxf(v2, 0.f);
            a3 += fmaxf(v3, 0.f);
        }
    }

    float* dst = &g_aggp[blockIdx.y][j * ND];
    *(float2*)&dst[kA] = make_float2(a0, a1);
    *(float2*)&dst[kB] = make_float2(a2, a3);
}

// ---------------- K5: update MLP  n_out = relu([n, sum(aggp)] @ uW + ub) ----------------
__global__ __launch_bounds__(128) void k_upd(
    const float* __restrict__ nin,
    const float* __restrict__ uW, const float* __restrict__ ub,
    float* __restrict__ nout)
{
    constexpr int NB = 2;
    __shared__ float xs[NB][2 * ND];
    const int k = threadIdx.x;
    const int n0 = blockIdx.x * NB;
    for (int idx = k; idx < NB * ND; idx += 128) {
        int nd = idx >> 7, t = idx & 127;
        int off = (n0 + nd) * ND + t;
        float s = g_aggp[0][off];
#pragma unroll
        for (int c = 1; c < NCH2; c++) s += g_aggp[c][off];
        xs[nd][t]      = nin[off];
        xs[nd][ND + t] = s;
    }
    __syncthreads();
    float acc[NB];
#pragma unroll
    for (int nd = 0; nd < NB; nd++) acc[nd] = 0.f;
    for (int t = 0; t < 2 * ND; t++) {
        float w = uW[t * ND + k];
#pragma unroll
        for (int nd = 0; nd < NB; nd++) acc[nd] += xs[nd][t] * w;
    }
    float bb = ub[k];
#pragma unroll
    for (int nd = 0; nd < NB; nd++)
        nout[(n0 + nd) * ND + k] = fmaxf(acc[nd] + bb, 0.f);
}

// ---------------- K6: P = n@Wc1[:128],  Q = n@Wc1[128:] + bc1 ----------------
// 128 threads: lower 64 compute P, upper 64 compute Q. NB=4 nodes/block.
__global__ __launch_bounds__(128) void k_pq(
    const float* __restrict__ nin,
    const float* __restrict__ Wc1, const float* __restrict__ bc1)
{
    constexpr int NB = 4;
    __shared__ float xs[NB][ND];
    const int half = threadIdx.x >> 6;      // 0 -> P, 1 -> Q
    const int k = threadIdx.x & 63;
    const int n0 = blockIdx.x * NB;
    for (int idx = threadIdx.x; idx < NB * ND; idx += 128)
        xs[idx >> 7][idx & 127] = nin[n0 * ND + idx];
    __syncthreads();
    float acc[NB];
#pragma unroll
    for (int nd = 0; nd < NB; nd++) acc[nd] = 0.f;
    const float* Wcol = &Wc1[half * ND * 64];
    for (int t = 0; t < ND; t++) {
        float w = Wcol[t * 64 + k];
#pragma unroll
        for (int nd = 0; nd < NB; nd++) acc[nd] += xs[nd][t] * w;
    }
    float bb = half ? bc1[k] : 0.f;
    float* dst = half ? g_Q : g_P;
#pragma unroll
    for (int nd = 0; nd < NB; nd++)
        dst[(n0 + nd) * 64 + k] = acc[nd] + bb;
}

// ---------------- K7: pairwise scores (relu(P_i+Q_j) @ Wc2 -> sigmoid) ----------------
__global__ __launch_bounds__(256) void k_scores(
    const float* __restrict__ Wc2, const float* __restrict__ bc2,
    float* __restrict__ out)
{
    __shared__ float Ps[16][65], Qs[16][65], ws[64];
    const int tid = threadIdx.x;
    const int tx = tid & 15, ty = tid >> 4;
    const int j0 = blockIdx.x * 16, i0 = blockIdx.y * 16;

    for (int idx = tid; idx < 16 * 64; idx += 256) {
        int r = idx >> 6, c = idx & 63;
        Ps[r][c] = g_P[(i0 + r) * 64 + c];
        Qs[r][c] = g_Q[(j0 + r) * 64 + c];
    }
    if (tid < 64) ws[tid] = Wc2[tid];
    __syncthreads();

    float acc = 0.f;
#pragma unroll 8
    for (int t = 0; t < 64; t++)
        acc += fmaxf(Ps[ty][t] + Qs[tx][t], 0.f) * ws[t];
    acc += bc2[0];
    float s = 1.f / (1.f + expf(-acc));
    const int i = i0 + ty, j = j0 + tx;
    out[i * NN + j] = (i == j) ? 0.f : s;
}

// ---------------- launch ----------------
extern "C" void kernel_launch(void* const* d_in, const int* in_sizes, int n_in,
                              void* d_out, int out_size)
{
    const float* X   = (const float*)d_in[0];
    const float* pos = (const float*)d_in[1];
    const float* W1  = (const float*)d_in[2];
    const float* b1  = (const float*)d_in[3];
    const float* W2  = (const float*)d_in[4];
    const float* b2  = (const float*)d_in[5];
    const float* lng = (const float*)d_in[6];
    const float* lnb = (const float*)d_in[7];
    const float* We1 = (const float*)d_in[8];
    const float* be1 = (const float*)d_in[9];
    const float* We2 = (const float*)d_in[10];
    const float* be2 = (const float*)d_in[11];
    const float* mW1 = (const float*)d_in[12];
    const float* mb1 = (const float*)d_in[13];
    const float* uW1 = (const float*)d_in[14];
    const float* ub1 = (const float*)d_in[15];
    const float* mW2 = (const float*)d_in[16];
    const float* mb2 = (const float*)d_in[17];
    const float* uW2 = (const float*)d_in[18];
    const float* ub2 = (const float*)d_in[19];
    const float* Wc1 = (const float*)d_in[20];
    const float* bc1 = (const float*)d_in[21];
    const float* Wc2 = (const float*)d_in[22];
    const float* bc2 = (const float*)d_in[23];

    float* out   = (float*)d_out;
    float* out_n = out;             // [512*128] node features
    float* out_s = out + NN * ND;   // [512*512] scores

    float *pN = nullptr, *pN2 = nullptr;
    cudaGetSymbolAddress((void**)&pN,  g_n);
    cudaGetSymbolAddress((void**)&pN2, g_n2);

    // fused: node projector+LN (blocks 0..255) + edge encoder (blocks 256..767)
    k_pre<<<768, 128>>>(X, W1, b1, W2, b2, lng, lnb,
                        pos, We1, be1, We2, be2);

    // MPN layer 1
    k_ab<<<256, 128>>>(pN, mW1, mb1);
    k_agg<<<dim3(128, NCH2), 128>>>(mW1);
    k_upd<<<256, 128>>>(pN, uW1, ub1, pN2);

    // MPN layer 2 (final node features written straight into d_out)
    k_ab<<<256, 128>>>(pN2, mW2, mb2);
    k_agg<<<dim3(128, NCH2), 128>>>(mW2);
    k_upd<<<256, 128>>>(pN2, uW2, ub2, out_n);

    // classifier
    k_pq<<<128, 128>>>(out_n, Wc1, bc1);
    k_scores<<<dim3(32, 32), 256>>>(Wc2, bc2, out_s);
}